// round 2
// baseline (speedup 1.0000x reference)
#include <cuda_runtime.h>
#include <cstdint>

#define T_TOK 8192
#define DIM   1024
#define NE    8
#define TOPK  2
#define NP    (T_TOK * TOPK)   // 16384 (token,expert) pairs

// ---------------- scratch (static device globals: allocation-free) ----------
__device__ float g_H[(size_t)NP * DIM];   // 64 MB: relu(x @ W1^T), permuted order
__device__ float g_Y[(size_t)NP * DIM];   // 64 MB: w * relu(h @ W2^T), flat-slot order
__device__ int   g_perm_src[NP];          // permuted pos -> original flat slot
__device__ int   g_counts[NE];
__device__ int   g_offsets[NE];
__device__ int   g_cursor[NE];

// ---------------- grouping kernels ------------------------------------------
__global__ void k_zero_counts() {
    if (threadIdx.x < NE) g_counts[threadIdx.x] = 0;
}

__global__ void k_hist(const int* __restrict__ idx) {
    int i = blockIdx.x * blockDim.x + threadIdx.x;
    if (i < NP) atomicAdd(&g_counts[idx[i]], 1);
}

__global__ void k_scan() {
    int s = 0;
    for (int e = 0; e < NE; ++e) {
        g_offsets[e] = s;
        g_cursor[e]  = s;
        s += g_counts[e];
    }
}

__global__ void k_scatter(const int* __restrict__ idx) {
    int i = blockIdx.x * blockDim.x + threadIdx.x;
    if (i < NP) {
        int e = idx[i];
        int p = atomicAdd(&g_cursor[e], 1);
        g_perm_src[p] = i;
    }
}

// ---------------- packed f32x2 helpers ---------------------------------------
__device__ __forceinline__ unsigned long long pack2(float lo, float hi) {
    unsigned long long r;
    asm("mov.b64 %0, {%1, %2};" : "=l"(r) : "f"(lo), "f"(hi));
    return r;
}
__device__ __forceinline__ void fma2(unsigned long long& d,
                                     unsigned long long a,
                                     unsigned long long b) {
    asm("fma.rn.f32x2 %0, %1, %2, %0;" : "+l"(d) : "l"(a), "l"(b));
}
__device__ __forceinline__ void unpack2(unsigned long long v, float& lo, float& hi) {
    asm("mov.b64 {%0, %1}, %2;" : "=f"(lo), "=f"(hi) : "l"(v));
}

// ---------------- grouped GEMM ------------------------------------------------
// C[TM=128, TN=128] tiles over (rows of this expert's segment) x (output dim).
// A and B are both K-major (row-major with D contiguous): C = A . B^T.
// STAGE 1: A = x (rows gathered via g_perm_src, token = slot>>1), B = W1[e],
//          epilogue relu -> g_H[permuted row].
// STAGE 2: A = g_H (contiguous permuted rows), B = W2[e],
//          epilogue relu * flat_weight -> g_Y[original flat slot].
#define TM  128
#define TN  128
#define TKK 16
#define SSTR (TM + 4)

template <int STAGE>
__global__ __launch_bounds__(256)
void k_gemm(const float* __restrict__ X,
            const float* __restrict__ Wall,
            const float* __restrict__ fw)
{
    const int e   = blockIdx.z;
    const int cnt = g_counts[e];
    const int off = g_offsets[e];
    const int m0  = blockIdx.y * TM;
    if (m0 >= cnt) return;
    const int n0  = blockIdx.x * TN;

    const float* __restrict__ W = Wall + (size_t)e * DIM * DIM;
    const float* __restrict__ A = (STAGE == 1) ? X : g_H;

    __shared__ float As[TKK][SSTR];
    __shared__ float Bs[TKK][SSTR];
    __shared__ int   rowA[TM];

    const int tid = threadIdx.x;
    if (tid < TM) {
        int r = min(m0 + tid, cnt - 1);   // clamp tail rows (stores masked later)
        int p = off + r;
        rowA[tid] = (STAGE == 1) ? (g_perm_src[p] >> 1) : p;
    }
    __syncthreads();

    const int tx = tid & 15;   // 16 col groups
    const int ty = tid >> 4;   // 16 row groups

    unsigned long long acc[8][4];
    #pragma unroll
    for (int i = 0; i < 8; ++i)
        #pragma unroll
        for (int j = 0; j < 4; ++j) acc[i][j] = 0ull;

    for (int k0 = 0; k0 < DIM; k0 += TKK) {
        // cooperative loads: 128x16 A tile + 128x16 B tile, float4 each
        #pragma unroll
        for (int q = 0; q < 2; ++q) {
            int id = tid + 256 * q;
            int m  = id >> 2;
            int kc = (id & 3) << 2;
            float4 av = *(const float4*)&A[(size_t)rowA[m] * DIM + k0 + kc];
            As[kc + 0][m] = av.x; As[kc + 1][m] = av.y;
            As[kc + 2][m] = av.z; As[kc + 3][m] = av.w;
            float4 bv = *(const float4*)&W[(size_t)(n0 + m) * DIM + k0 + kc];
            Bs[kc + 0][m] = bv.x; Bs[kc + 1][m] = bv.y;
            Bs[kc + 2][m] = bv.z; Bs[kc + 3][m] = bv.w;
        }
        __syncthreads();

        #pragma unroll
        for (int k = 0; k < TKK; ++k) {
            float4 a0 = *(const float4*)&As[k][ty * 4];
            float4 a1 = *(const float4*)&As[k][64 + ty * 4];
            float4 b0 = *(const float4*)&Bs[k][tx * 4];
            float4 b1 = *(const float4*)&Bs[k][64 + tx * 4];

            unsigned long long b2[4];
            b2[0] = pack2(b0.x, b0.y); b2[1] = pack2(b0.z, b0.w);
            b2[2] = pack2(b1.x, b1.y); b2[3] = pack2(b1.z, b1.w);

            float av[8] = {a0.x, a0.y, a0.z, a0.w, a1.x, a1.y, a1.z, a1.w};
            #pragma unroll
            for (int i = 0; i < 8; ++i) {
                unsigned long long a2 = pack2(av[i], av[i]);
                #pragma unroll
                for (int j = 0; j < 4; ++j) fma2(acc[i][j], a2, b2[j]);
            }
        }
        __syncthreads();
    }

    // epilogue
    #pragma unroll
    for (int ib = 0; ib < 2; ++ib) {
        #pragma unroll
        for (int ii = 0; ii < 4; ++ii) {
            int m  = ib * 64 + ty * 4 + ii;
            int gr = m0 + m;
            if (gr >= cnt) continue;
            int p = off + gr;
            int ar = ib * 4 + ii;

            float   w = 1.0f;
            size_t  dstRow;
            float*  base;
            if (STAGE == 1) {
                dstRow = (size_t)p;
                base   = g_H;
            } else {
                int src = g_perm_src[p];
                w       = fw[src];
                dstRow  = (size_t)src;
                base    = g_Y;
            }
            float* dst = base + dstRow * DIM;

            #pragma unroll
            for (int jb = 0; jb < 2; ++jb) {
                float x0, x1, x2, x3;
                unpack2(acc[ar][jb * 2 + 0], x0, x1);
                unpack2(acc[ar][jb * 2 + 1], x2, x3);
                float4 v;
                v.x = fmaxf(x0, 0.0f) * w;
                v.y = fmaxf(x1, 0.0f) * w;
                v.z = fmaxf(x2, 0.0f) * w;
                v.w = fmaxf(x3, 0.0f) * w;
                *(float4*)&dst[n0 + jb * 64 + tx * 4] = v;
            }
        }
    }
}

// ---------------- combine: out[t] = Y[2t] + Y[2t+1] (weights already applied) -
__global__ void k_combine(float* __restrict__ out) {
    int i = blockIdx.x * blockDim.x + threadIdx.x;   // float4 index over T*D/4
    if (i >= T_TOK * DIM / 4) return;
    int t = i / (DIM / 4);
    const float4* y = (const float4*)g_Y;
    float4 a = y[(size_t)i + (size_t)t * (DIM / 4)];
    float4 b = y[(size_t)i + (size_t)t * (DIM / 4) + (DIM / 4)];
    float4 o;
    o.x = a.x + b.x; o.y = a.y + b.y; o.z = a.z + b.z; o.w = a.w + b.w;
    ((float4*)out)[i] = o;
}

// ---------------- launch ------------------------------------------------------
extern "C" void kernel_launch(void* const* d_in, const int* in_sizes, int n_in,
                              void* d_out, int out_size) {
    const float* x   = (const float*)d_in[0];   // [T, D]
    const int*   fei = (const int*)d_in[1];     // [T*K]
    const float* few = (const float*)d_in[2];   // [T*K]
    const float* W1  = (const float*)d_in[3];   // [E, D, D]
    const float* W2  = (const float*)d_in[4];   // [E, D, D]
    float* out = (float*)d_out;                 // [T, D]

    k_zero_counts<<<1, 32>>>();
    k_hist<<<NP / 256, 256>>>(fei);
    k_scan<<<1, 1>>>();
    k_scatter<<<NP / 256, 256>>>(fei);

    dim3 grid(DIM / TN, NP / TM, NE);   // (8 ntiles, 128 mtiles max, 8 experts)
    k_gemm<1><<<grid, 256>>>(x, W1, few);
    k_gemm<2><<<grid, 256>>>(x, W2, few);

    k_combine<<<(T_TOK * DIM / 4 + 255) / 256, 256>>>(out);
}

// round 6
// speedup vs baseline: 2.2949x; 2.2949x over previous
#include <cuda_runtime.h>
#include <cuda_bf16.h>
#include <cstdint>

#define T_TOK 8192
#define DIM   1024
#define NE    8
#define NP    (T_TOK * 2)      // 16384 (token,expert) pairs

#define TM    128
#define TN    128
#define TK    32               // bf16 K per pipeline stage
#define NCH   (DIM / TK)       // 32 chunks
#define NSTG  3

// stage layout: Ah(8K) Al(8K) Bh(8K) Bl(8K) = 32KB
#define STG_BYTES 32768u
#define OFF_AH 0u
#define OFF_AL 8192u
#define OFF_BH 16384u
#define OFF_BL 24576u
#define SM_STG0 1024u
#define SM_TOTAL (1024 + NSTG * 32768)

// ---------------- static device scratch (allocation-free) --------------------
__device__ __nv_bfloat16 g_Xh[(size_t)NP * DIM], g_Xl[(size_t)NP * DIM];
__device__ __nv_bfloat16 g_Hh[(size_t)NP * DIM], g_Hl[(size_t)NP * DIM];
__device__ __nv_bfloat16 g_W1h[(size_t)NE * DIM * DIM], g_W1l[(size_t)NE * DIM * DIM];
__device__ __nv_bfloat16 g_W2h[(size_t)NE * DIM * DIM], g_W2l[(size_t)NE * DIM * DIM];
__device__ float g_Y[(size_t)NP * DIM];
__device__ int g_perm_src[NP];
__device__ int g_counts[NE], g_offsets[NE], g_cursor[NE];

// ---------------- PTX helpers ------------------------------------------------
__device__ __forceinline__ uint32_t smem_u32(const void* p) {
    uint32_t a;
    asm("{ .reg .u64 t; cvta.to.shared.u64 t, %1; cvt.u32.u64 %0, t; }" : "=r"(a) : "l"(p));
    return a;
}
__device__ __forceinline__ void cpa16(uint32_t dst, const void* src) {
    asm volatile("cp.async.cg.shared.global [%0], [%1], 16;" :: "r"(dst), "l"(src));
}
#define CP_COMMIT() asm volatile("cp.async.commit_group;" ::: "memory")
#define CP_WAIT(n)  asm volatile("cp.async.wait_group %0;" :: "n"(n) : "memory")

__device__ __forceinline__ void ldsm4(uint32_t& r0, uint32_t& r1, uint32_t& r2,
                                      uint32_t& r3, uint32_t addr) {
    asm volatile("ldmatrix.sync.aligned.m8n8.x4.shared.b16 {%0,%1,%2,%3}, [%4];"
                 : "=r"(r0), "=r"(r1), "=r"(r2), "=r"(r3) : "r"(addr));
}
__device__ __forceinline__ void mma16816(float* c, const uint32_t* a,
                                         uint32_t b0, uint32_t b1) {
    asm volatile("mma.sync.aligned.m16n8k16.row.col.f32.bf16.bf16.f32 "
                 "{%0,%1,%2,%3}, {%4,%5,%6,%7}, {%8,%9}, {%0,%1,%2,%3};"
                 : "+f"(c[0]), "+f"(c[1]), "+f"(c[2]), "+f"(c[3])
                 : "r"(a[0]), "r"(a[1]), "r"(a[2]), "r"(a[3]), "r"(b0), "r"(b1));
}

// 16B-chunk XOR swizzle: rows of 64B (4 chunks); conflict-free for 8-row ldmatrix.
__device__ __forceinline__ uint32_t sw_off(int r, int c16) {
    return (uint32_t)(r * 64 + ((c16 ^ ((r >> 1) & 3)) << 4));
}

// ---------------- grouping ---------------------------------------------------
__global__ void k_zero_counts() { if (threadIdx.x < NE) g_counts[threadIdx.x] = 0; }
__global__ void k_hist(const int* __restrict__ idx) {
    int i = blockIdx.x * blockDim.x + threadIdx.x;
    if (i < NP) atomicAdd(&g_counts[idx[i]], 1);
}
__global__ void k_scan() {
    int s = 0;
    for (int e = 0; e < NE; ++e) { g_offsets[e] = s; g_cursor[e] = s; s += g_counts[e]; }
}
__global__ void k_scatter(const int* __restrict__ idx) {
    int i = blockIdx.x * blockDim.x + threadIdx.x;
    if (i < NP) { int e = idx[i]; g_perm_src[atomicAdd(&g_cursor[e], 1)] = i; }
}

// ---------------- fp32 -> bf16 hi/lo converts --------------------------------
union B8 { __nv_bfloat16 b[8]; uint4 u; };

__device__ __forceinline__ void split8(const float* v, B8& h, B8& l) {
    #pragma unroll
    for (int j = 0; j < 8; ++j) {
        __nv_bfloat16 hv = __float2bfloat16(v[j]);
        h.b[j] = hv;
        l.b[j] = __float2bfloat16(v[j] - __bfloat162float(hv));
    }
}

__global__ void k_convert_x(const float* __restrict__ x) {
    int i = blockIdx.x * blockDim.x + threadIdx.x;
    if (i >= NP * (DIM / 8)) return;
    int p  = i >> 7;
    int c8 = (i & 127) << 3;
    int tok = g_perm_src[p] >> 1;
    float v[8];
    *(float4*)&v[0] = *(const float4*)&x[(size_t)tok * DIM + c8];
    *(float4*)&v[4] = *(const float4*)&x[(size_t)tok * DIM + c8 + 4];
    B8 h, l; split8(v, h, l);
    *(uint4*)&g_Xh[(size_t)p * DIM + c8] = h.u;
    *(uint4*)&g_Xl[(size_t)p * DIM + c8] = l.u;
}

__global__ void k_convert_w(const float* __restrict__ W, int which) {
    size_t i = (size_t)blockIdx.x * blockDim.x + threadIdx.x;
    if (i >= (size_t)NE * DIM * DIM / 8) return;
    size_t b0 = i * 8;
    float v[8];
    *(float4*)&v[0] = *(const float4*)&W[b0];
    *(float4*)&v[4] = *(const float4*)&W[b0 + 4];
    B8 h, l; split8(v, h, l);
    __nv_bfloat16* dh = which ? g_W2h : g_W1h;
    __nv_bfloat16* dl = which ? g_W2l : g_W1l;
    *(uint4*)&dh[b0] = h.u;
    *(uint4*)&dl[b0] = l.u;
}

// ---------------- mma.sync grouped GEMM --------------------------------------
template <int STAGE>
__global__ __launch_bounds__(256, 2)
void k_gemm(const float* __restrict__ fw)
{
    extern __shared__ __align__(1024) char smem[];
    const int e   = blockIdx.z;
    const int cnt = g_counts[e];
    const int m0  = blockIdx.y * TM;
    if (m0 >= cnt) return;
    const int off = g_offsets[e];
    const int n0  = blockIdx.x * TN;
    const int tid = threadIdx.x;
    const int wid  = tid >> 5;
    const int lane = tid & 31;

    const uint32_t sb = smem_u32(smem);
    int* rowA = (int*)smem;
    if (tid < TM) rowA[tid] = off + min(m0 + tid, cnt - 1);
    __syncthreads();

    const __nv_bfloat16* __restrict__ Ah = (STAGE == 1) ? g_Xh : g_Hh;
    const __nv_bfloat16* __restrict__ Al = (STAGE == 1) ? g_Xl : g_Hl;
    const __nv_bfloat16* __restrict__ Bh =
        ((STAGE == 1) ? g_W1h : g_W2h) + (size_t)e * DIM * DIM;
    const __nv_bfloat16* __restrict__ Bl =
        ((STAGE == 1) ? g_W1l : g_W2l) + (size_t)e * DIM * DIM;

    // per-thread load coords: 2 iters, id = tid + 256*q -> r = id>>2, c16 = id&3
    const int r0l = tid >> 2, c0l = tid & 3;

    auto load_stage = [&](int c) {
        const int kc0 = c * TK;
        const uint32_t stg = SM_STG0 + (uint32_t)(c % NSTG) * STG_BYTES;
        #pragma unroll
        for (int q = 0; q < 2; ++q) {
            const int r = r0l + 64 * q;
            const uint32_t sw = sw_off(r, c0l);
            const size_t ga = (size_t)rowA[r] * DIM + kc0 + c0l * 8;
            cpa16(sb + stg + OFF_AH + sw, Ah + ga);
            cpa16(sb + stg + OFF_AL + sw, Al + ga);
            const size_t gb = (size_t)(n0 + r) * DIM + kc0 + c0l * 8;
            cpa16(sb + stg + OFF_BH + sw, Bh + gb);
            cpa16(sb + stg + OFF_BL + sw, Bl + gb);
        }
        CP_COMMIT();
    };

    // warp tiling: wm in {0,1} (64-row band), wn in {0..3} (32-col band)
    const int wm = wid & 1, wn = wid >> 1;
    const int lrow = lane & 15;          // ldmatrix row-within-16
    const int lhi  = lane >> 4;          // chunk select bit

    float acc[4][4][4];
    #pragma unroll
    for (int i = 0; i < 4; ++i)
        #pragma unroll
        for (int j = 0; j < 4; ++j)
            #pragma unroll
            for (int k = 0; k < 4; ++k) acc[i][j][k] = 0.0f;

    // prologue
    load_stage(0);
    load_stage(1);

    for (int c = 0; c < NCH; ++c) {
        CP_WAIT(NSTG - 2);
        __syncthreads();
        if (c + NSTG - 1 < NCH) load_stage(c + NSTG - 1);
        else CP_COMMIT();

        const uint32_t stg = SM_STG0 + (uint32_t)(c % NSTG) * STG_BYTES;
        #pragma unroll
        for (int s = 0; s < 2; ++s) {
            const int csel = 2 * s + lhi;

            uint32_t ah[4][4];
            #pragma unroll
            for (int mt = 0; mt < 4; ++mt) {
                int r = wm * 64 + mt * 16 + lrow;
                ldsm4(ah[mt][0], ah[mt][1], ah[mt][2], ah[mt][3],
                      sb + stg + OFF_AH + sw_off(r, csel));
            }
            uint32_t bh[4][2];
            #pragma unroll
            for (int g = 0; g < 2; ++g) {
                int r = wn * 32 + g * 16 + lrow;
                uint32_t t0, t1, t2, t3;
                ldsm4(t0, t1, t2, t3, sb + stg + OFF_BH + sw_off(r, csel));
                bh[g * 2 + 0][0] = t0; bh[g * 2 + 0][1] = t2;
                bh[g * 2 + 1][0] = t1; bh[g * 2 + 1][1] = t3;
            }
            #pragma unroll
            for (int mt = 0; mt < 4; ++mt)
                #pragma unroll
                for (int nt = 0; nt < 4; ++nt)
                    mma16816(acc[mt][nt], ah[mt], bh[nt][0], bh[nt][1]);

            // hl term: Ah x Bl
            uint32_t bl[4][2];
            #pragma unroll
            for (int g = 0; g < 2; ++g) {
                int r = wn * 32 + g * 16 + lrow;
                uint32_t t0, t1, t2, t3;
                ldsm4(t0, t1, t2, t3, sb + stg + OFF_BL + sw_off(r, csel));
                bl[g * 2 + 0][0] = t0; bl[g * 2 + 0][1] = t2;
                bl[g * 2 + 1][0] = t1; bl[g * 2 + 1][1] = t3;
            }
            #pragma unroll
            for (int mt = 0; mt < 4; ++mt)
                #pragma unroll
                for (int nt = 0; nt < 4; ++nt)
                    mma16816(acc[mt][nt], ah[mt], bl[nt][0], bl[nt][1]);

            // lh term: Al x Bh
            uint32_t al[4][4];
            #pragma unroll
            for (int mt = 0; mt < 4; ++mt) {
                int r = wm * 64 + mt * 16 + lrow;
                ldsm4(al[mt][0], al[mt][1], al[mt][2], al[mt][3],
                      sb + stg + OFF_AL + sw_off(r, csel));
            }
            #pragma unroll
            for (int mt = 0; mt < 4; ++mt)
                #pragma unroll
                for (int nt = 0; nt < 4; ++nt)
                    mma16816(acc[mt][nt], al[mt], bh[nt][0], bh[nt][1]);
        }
        __syncthreads();
    }

    // ---------------- epilogue ----------------
    const int lq = lane >> 2;            // 0..7: row within m8
    const int lr = lane & 3;             // col pair
    #pragma unroll
    for (int mt = 0; mt < 4; ++mt) {
        #pragma unroll
        for (int half = 0; half < 2; ++half) {
            const int m  = wm * 64 + mt * 16 + half * 8 + lq;
            const int gr = m0 + m;
            if (gr >= cnt) continue;
            const int p = off + gr;
            int dstrow = p;
            float wt = 1.0f;
            if (STAGE == 2) { dstrow = g_perm_src[p]; wt = fw[dstrow]; }
            #pragma unroll
            for (int nt = 0; nt < 4; ++nt) {
                const int col = n0 + wn * 32 + nt * 8 + lr * 2;
                float v0 = fmaxf(acc[mt][nt][half * 2 + 0], 0.0f);
                float v1 = fmaxf(acc[mt][nt][half * 2 + 1], 0.0f);
                if (STAGE == 1) {
                    __nv_bfloat16 h0 = __float2bfloat16(v0);
                    __nv_bfloat16 h1 = __float2bfloat16(v1);
                    __nv_bfloat16 l0 = __float2bfloat16(v0 - __bfloat162float(h0));
                    __nv_bfloat16 l1 = __float2bfloat16(v1 - __bfloat162float(h1));
                    __nv_bfloat162 hp; hp.x = h0; hp.y = h1;
                    __nv_bfloat162 lp; lp.x = l0; lp.y = l1;
                    *(__nv_bfloat162*)&g_Hh[(size_t)p * DIM + col] = hp;
                    *(__nv_bfloat162*)&g_Hl[(size_t)p * DIM + col] = lp;
                } else {
                    float2 o; o.x = v0 * wt; o.y = v1 * wt;
                    *(float2*)&g_Y[(size_t)dstrow * DIM + col] = o;
                }
            }
        }
    }
}

// ---------------- combine ----------------------------------------------------
__global__ void k_combine(float* __restrict__ out) {
    int i = blockIdx.x * blockDim.x + threadIdx.x;
    if (i >= T_TOK * DIM / 4) return;
    int t = i / (DIM / 4);
    const float4* y = (const float4*)g_Y;
    float4 a = y[(size_t)i + (size_t)t * (DIM / 4)];
    float4 b = y[(size_t)i + (size_t)t * (DIM / 4) + (DIM / 4)];
    float4 o; o.x = a.x + b.x; o.y = a.y + b.y; o.z = a.z + b.z; o.w = a.w + b.w;
    ((float4*)out)[i] = o;
}

// ---------------- launch ------------------------------------------------------
extern "C" void kernel_launch(void* const* d_in, const int* in_sizes, int n_in,
                              void* d_out, int out_size) {
    const float* x   = (const float*)d_in[0];
    const int*   fei = (const int*)d_in[1];
    const float* few = (const float*)d_in[2];
    const float* W1  = (const float*)d_in[3];
    const float* W2  = (const float*)d_in[4];
    float* out = (float*)d_out;

    cudaFuncSetAttribute(k_gemm<1>, cudaFuncAttributeMaxDynamicSharedMemorySize, SM_TOTAL);
    cudaFuncSetAttribute(k_gemm<2>, cudaFuncAttributeMaxDynamicSharedMemorySize, SM_TOTAL);

    k_zero_counts<<<1, 32>>>();
    k_hist<<<NP / 256, 256>>>(fei);
    k_scan<<<1, 1>>>();
    k_scatter<<<NP / 256, 256>>>(fei);

    k_convert_x<<<(NP * (DIM / 8) + 255) / 256, 256>>>(x);
    k_convert_w<<<(NE * DIM * DIM / 8 + 255) / 256, 256>>>(W1, 0);
    k_convert_w<<<(NE * DIM * DIM / 8 + 255) / 256, 256>>>(W2, 1);

    dim3 grid(DIM / TN, NP / TM, NE);
    k_gemm<1><<<grid, 256, SM_TOTAL>>>(few);
    k_gemm<2><<<grid, 256, SM_TOTAL>>>(few);

    k_combine<<<(T_TOK * DIM / 4 + 255) / 256, 256>>>(out);
}